// round 9
// baseline (speedup 1.0000x reference)
#include <cuda_runtime.h>
#include <cstdint>

// PosRegressor_43482248904949 — batched bilinear shift with mirror boundary.
// images: (256,512,512,1) fp32, dxdy: (256,2) fp32 -> out: (256,512,512) fp32.
//
// R9: persistent single-wave grid. R8 tile body (10 front-batched LDG.128,
// uniform m=kx&3 register-window select, streaming STG.128) looped over a
// contiguous chunk of tiles per block:
//  - 592 blocks = 4 per SM, ONE wave: no wave-transition DRAM drain (~27
//    transitions in R8).
//  - stores are issue-only => next tile's load burst overlaps store drain.
//  - contiguous y-chunks: next tile's top row = prev tile's bottom row (L1 hit).

#define H 512
#define W 512
#define NTHREADS 256
#define TILES_TOTAL (256 * 64)      // 64 y-tiles (8 rows) per image
#define GRID_BLOCKS 592             // 4 * 148 (one wave on 148- or 152-SM part)

__device__ __forceinline__ int mirror_idx(int idx, int n) {
    const int p = 2 * (n - 1);
    int i = idx < 0 ? -idx : idx;
    i %= p;
    return (i >= n) ? (p - i) : i;
}

template <int M>
__device__ __forceinline__ void run_tile(
    const float* __restrict__ imb,
    float* __restrict__ outp,
    const int* __restrict__ roff,    // 5 mirrored input row offsets (elems)
    int a0,                          // 4-aligned input start column
    float fx, float fy)
{
    // ---- Load phase: 10 independent LDG.128 front-batched (deep MLP).
    float v[5][8];
    const bool interior = (a0 >= 0) & (a0 + 7 < W);
    if (interior) {
        #pragma unroll
        for (int r = 0; r < 5; ++r) {
            const float4 A = *reinterpret_cast<const float4*>(imb + roff[r] + a0);
            const float4 B = *reinterpret_cast<const float4*>(imb + roff[r] + a0 + 4);
            v[r][0]=A.x; v[r][1]=A.y; v[r][2]=A.z; v[r][3]=A.w;
            v[r][4]=B.x; v[r][5]=B.y; v[r][6]=B.z; v[r][7]=B.w;
        }
    } else {
        #pragma unroll
        for (int r = 0; r < 5; ++r)
            #pragma unroll
            for (int e = 0; e < 8; ++e)
                v[r][e] = imb[roff[r] + mirror_idx(a0 + e, W)];
    }

    // ---- Horizontal lerp (constant fx), window at uniform offset M.
    float h[5][4];
    #pragma unroll
    for (int r = 0; r < 5; ++r)
        #pragma unroll
        for (int j = 0; j < 4; ++j)
            h[r][j] = fmaf(fx, v[r][M + j + 1] - v[r][M + j], v[r][M + j]);

    // ---- Vertical lerp + streaming STG.128.
    #pragma unroll
    for (int r = 0; r < 4; ++r) {
        float4 o;
        o.x = fmaf(fy, h[r + 1][0] - h[r][0], h[r][0]);
        o.y = fmaf(fy, h[r + 1][1] - h[r][1], h[r][1]);
        o.z = fmaf(fy, h[r + 1][2] - h[r][2], h[r][2]);
        o.w = fmaf(fy, h[r + 1][3] - h[r][3], h[r][3]);
        __stcs(reinterpret_cast<float4*>(outp), o);
        outp += W;
    }
}

__global__ void __launch_bounds__(NTHREADS, 4)
shift_bilinear_kernel(const float* __restrict__ img,
                      const float* __restrict__ dxdy,
                      float* __restrict__ out) {
    const int tid  = threadIdx.x;
    const int wid  = tid >> 5;
    const int lane = tid & 31;

    const int cw = (wid & 3) * 128;         // warp column tile
    const int h0 = (wid >> 2) * 4;          // row half: rows [h0, h0+4)

    // Contiguous chunk of tiles for this block (one wave, ~28 tiles each).
    const int chunk = (TILES_TOTAL + GRID_BLOCKS - 1) / GRID_BLOCKS;
    const int t0 = blockIdx.x * chunk;
    const int t1 = min(t0 + chunk, TILES_TOTAL);

    for (int t = t0; t < t1; ++t) {
        const int b  = t >> 6;              // image
        const int yb = (t & 63) << 3;       // first output row of tile

        const float dy = dxdy[2 * b + 0];
        const float dx = dxdy[2 * b + 1];
        const float ndx = -dx, ndy = -dy;
        const float kxf = floorf(ndx); const int kx = (int)kxf; const float fx = ndx - kxf;
        const float kyf = floorf(ndy); const int ky = (int)kyf; const float fy = ndy - kyf;

        const int m  = kx & 3;              // uniform across all threads
        const int a0 = cw + 4 * lane + kx - m;

        const size_t base = (size_t)b * (H * W);
        const float* __restrict__ imb = img + base;
        float* __restrict__ outp = out + base + (size_t)(yb + h0) * W + cw + 4 * lane;

        const int ybase = yb + ky + h0;
        int roff[5];
        #pragma unroll
        for (int r = 0; r < 5; ++r)
            roff[r] = mirror_idx(ybase + r, H) * W;

        switch (m) {
            case 0: run_tile<0>(imb, outp, roff, a0, fx, fy); break;
            case 1: run_tile<1>(imb, outp, roff, a0, fx, fy); break;
            case 2: run_tile<2>(imb, outp, roff, a0, fx, fy); break;
            default: run_tile<3>(imb, outp, roff, a0, fx, fy); break;
        }
    }
}

extern "C" void kernel_launch(void* const* d_in, const int* in_sizes, int n_in,
                              void* d_out, int out_size) {
    const float* images = (const float*)d_in[0];  // (256,512,512,1)
    const float* dxdy   = (const float*)d_in[1];  // (256,2)
    float* out = (float*)d_out;                   // (256,512,512)

    shift_bilinear_kernel<<<GRID_BLOCKS, NTHREADS>>>(images, dxdy, out);
}

// round 10
// speedup vs baseline: 1.0338x; 1.0338x over previous
#include <cuda_runtime.h>
#include <cstdint>

// PosRegressor_43482248904949 — batched bilinear shift with mirror boundary.
// images: (256,512,512,1) fp32, dxdy: (256,2) fp32 -> out: (256,512,512) fp32.
//
// R10: R8 tile body + GRID-STRIDE persistent loop (t = bid + i*592).
// Unlike R9's contiguous chunks, the stride mapping keeps the concurrent
// tile set identical to R8's waves (adjacent tiles -> L2 boundary-row
// sharing, correlated completion), while removing CTA churn and averaging
// cross-CTA L1tex-queue spread over ~27 iterations.

#define H 512
#define W 512
#define NTHREADS 256
#define TILES_TOTAL (256 * 64)      // 64 y-tiles (8 rows) per image
#define GRID_BLOCKS 592             // 4 per SM on 148 SMs = one resident set

__device__ __forceinline__ int mirror_idx(int idx, int n) {
    const int p = 2 * (n - 1);
    int i = idx < 0 ? -idx : idx;
    i %= p;
    return (i >= n) ? (p - i) : i;
}

template <int M>
__device__ __forceinline__ void run_tile(
    const float* __restrict__ imb,
    float* __restrict__ outp,
    const int* __restrict__ roff,    // 5 mirrored input row offsets (elems)
    int a0,                          // 4-aligned input start column
    float fx, float fy)
{
    // ---- Load phase: 10 independent LDG.128 front-batched (deep MLP).
    float v[5][8];
    const bool interior = (a0 >= 0) & (a0 + 7 < W);
    if (interior) {
        #pragma unroll
        for (int r = 0; r < 5; ++r) {
            const float4 A = *reinterpret_cast<const float4*>(imb + roff[r] + a0);
            const float4 B = *reinterpret_cast<const float4*>(imb + roff[r] + a0 + 4);
            v[r][0]=A.x; v[r][1]=A.y; v[r][2]=A.z; v[r][3]=A.w;
            v[r][4]=B.x; v[r][5]=B.y; v[r][6]=B.z; v[r][7]=B.w;
        }
    } else {
        #pragma unroll
        for (int r = 0; r < 5; ++r)
            #pragma unroll
            for (int e = 0; e < 8; ++e)
                v[r][e] = imb[roff[r] + mirror_idx(a0 + e, W)];
    }

    // ---- Horizontal lerp (constant fx), window at uniform offset M.
    float h[5][4];
    #pragma unroll
    for (int r = 0; r < 5; ++r)
        #pragma unroll
        for (int j = 0; j < 4; ++j)
            h[r][j] = fmaf(fx, v[r][M + j + 1] - v[r][M + j], v[r][M + j]);

    // ---- Vertical lerp + streaming STG.128.
    #pragma unroll
    for (int r = 0; r < 4; ++r) {
        float4 o;
        o.x = fmaf(fy, h[r + 1][0] - h[r][0], h[r][0]);
        o.y = fmaf(fy, h[r + 1][1] - h[r][1], h[r][1]);
        o.z = fmaf(fy, h[r + 1][2] - h[r][2], h[r][2]);
        o.w = fmaf(fy, h[r + 1][3] - h[r][3], h[r][3]);
        __stcs(reinterpret_cast<float4*>(outp), o);
        outp += W;
    }
}

__global__ void __launch_bounds__(NTHREADS, 4)
shift_bilinear_kernel(const float* __restrict__ img,
                      const float* __restrict__ dxdy,
                      float* __restrict__ out) {
    const int tid  = threadIdx.x;
    const int wid  = tid >> 5;
    const int lane = tid & 31;

    const int cw = (wid & 3) * 128;         // warp column tile
    const int h0 = (wid >> 2) * 4;          // row half: rows [h0, h0+4)
    const int cq = cw + 4 * lane;           // this thread's output quad column

    // Grid-stride persistent loop: concurrent set == R8's wave.
    for (int t = blockIdx.x; t < TILES_TOTAL; t += GRID_BLOCKS) {
        const int b  = t >> 6;              // image
        const int yb = (t & 63) << 3;       // first output row of tile

        const float dy = dxdy[2 * b + 0];
        const float dx = dxdy[2 * b + 1];
        const float ndx = -dx, ndy = -dy;
        const float kxf = floorf(ndx); const int kx = (int)kxf; const float fx = ndx - kxf;
        const float kyf = floorf(ndy); const int ky = (int)kyf; const float fy = ndy - kyf;

        const int m  = kx & 3;              // uniform across all threads
        const int a0 = cq + kx - m;         // 4-aligned input start

        const size_t base = (size_t)b * (H * W);
        const float* __restrict__ imb = img + base;
        float* __restrict__ outp = out + base + (size_t)(yb + h0) * W + cq;

        const int ybase = yb + ky + h0;
        int roff[5];
        #pragma unroll
        for (int r = 0; r < 5; ++r)
            roff[r] = mirror_idx(ybase + r, H) * W;

        switch (m) {
            case 0: run_tile<0>(imb, outp, roff, a0, fx, fy); break;
            case 1: run_tile<1>(imb, outp, roff, a0, fx, fy); break;
            case 2: run_tile<2>(imb, outp, roff, a0, fx, fy); break;
            default: run_tile<3>(imb, outp, roff, a0, fx, fy); break;
        }
    }
}

extern "C" void kernel_launch(void* const* d_in, const int* in_sizes, int n_in,
                              void* d_out, int out_size) {
    const float* images = (const float*)d_in[0];  // (256,512,512,1)
    const float* dxdy   = (const float*)d_in[1];  // (256,2)
    float* out = (float*)d_out;                   // (256,512,512)

    shift_bilinear_kernel<<<GRID_BLOCKS, NTHREADS>>>(images, dxdy, out);
}

// round 14
// speedup vs baseline: 1.1406x; 1.1032x over previous
#include <cuda_runtime.h>
#include <cstdint>

// PosRegressor_43482248904949 — batched bilinear shift with mirror boundary.
// images: (256,512,512,1) fp32, dxdy: (256,2) fp32 -> out: (256,512,512) fp32.
//
// R11: R8 tile body, 16-row blocks, two 4-row halves per warp off ONE prefix.
//  - per-warp setup (dxdy dependent load ~234cyc + floor/mirror ALU) amortized
//    over 8 rows instead of 4 (~3-4% of runtime reclaimed).
//  - half 2's first input row == half 1's last -> 2/10 LDG.128 are L1 hits.
//  - v[] dead between halves: peak regs == R8 (no R9/R10-style spills).
//  - launch-per-tile grid (8192 blocks) — persistence rejected (R9/R10).

#define H 512
#define W 512
#define NTHREADS 256

__device__ __forceinline__ int mirror_idx(int idx, int n) {
    const int p = 2 * (n - 1);
    int i = idx < 0 ? -idx : idx;
    i %= p;
    return (i >= n) ? (p - i) : i;
}

template <int M>
__device__ __forceinline__ void run_tile(
    const float* __restrict__ imb,
    float* __restrict__ outp,
    const int* __restrict__ roff,    // 5 mirrored input row offsets (elems)
    int a0,                          // 4-aligned input start column
    float fx, float fy)
{
    // ---- Load phase: 10 independent LDG.128 front-batched (deep MLP).
    float v[5][8];
    const bool interior = (a0 >= 0) & (a0 + 7 < W);
    if (interior) {
        #pragma unroll
        for (int r = 0; r < 5; ++r) {
            const float4 A = *reinterpret_cast<const float4*>(imb + roff[r] + a0);
            const float4 B = *reinterpret_cast<const float4*>(imb + roff[r] + a0 + 4);
            v[r][0]=A.x; v[r][1]=A.y; v[r][2]=A.z; v[r][3]=A.w;
            v[r][4]=B.x; v[r][5]=B.y; v[r][6]=B.z; v[r][7]=B.w;
        }
    } else {
        #pragma unroll
        for (int r = 0; r < 5; ++r)
            #pragma unroll
            for (int e = 0; e < 8; ++e)
                v[r][e] = imb[roff[r] + mirror_idx(a0 + e, W)];
    }

    // ---- Horizontal lerp (constant fx), window at uniform offset M.
    float h[5][4];
    #pragma unroll
    for (int r = 0; r < 5; ++r)
        #pragma unroll
        for (int j = 0; j < 4; ++j)
            h[r][j] = fmaf(fx, v[r][M + j + 1] - v[r][M + j], v[r][M + j]);

    // ---- Vertical lerp + streaming STG.128.
    #pragma unroll
    for (int r = 0; r < 4; ++r) {
        float4 o;
        o.x = fmaf(fy, h[r + 1][0] - h[r][0], h[r][0]);
        o.y = fmaf(fy, h[r + 1][1] - h[r][1], h[r][1]);
        o.z = fmaf(fy, h[r + 1][2] - h[r][2], h[r][2]);
        o.w = fmaf(fy, h[r + 1][3] - h[r][3], h[r][3]);
        __stcs(reinterpret_cast<float4*>(outp), o);
        outp += W;
    }
}

template <int M>
__device__ __forceinline__ void run_pair(
    const float* __restrict__ imb,
    float* __restrict__ outp,
    int ybase,                       // input row base for half 1
    int a0, float fx, float fy)
{
    int roff[5];
    #pragma unroll
    for (int r = 0; r < 5; ++r)
        roff[r] = mirror_idx(ybase + r, H) * W;
    run_tile<M>(imb, outp, roff, a0, fx, fy);

    #pragma unroll
    for (int r = 0; r < 5; ++r)
        roff[r] = mirror_idx(ybase + 4 + r, H) * W;   // row 4 reloads from L1
    run_tile<M>(imb, outp + 4 * W, roff, a0, fx, fy);
}

__global__ void __launch_bounds__(NTHREADS, 4)
shift_bilinear_kernel(const float* __restrict__ img,
                      const float* __restrict__ dxdy,
                      float* __restrict__ out) {
    const int b    = blockIdx.y;
    const int yb   = blockIdx.x * 16;       // 16 output rows per block
    const int tid  = threadIdx.x;
    const int wid  = tid >> 5;
    const int lane = tid & 31;

    const int cw = (wid & 3) * 128;         // warp column tile
    const int h0 = (wid >> 2) * 8;          // warp row range: [h0, h0+8)
    const int cq = cw + 4 * lane;           // this thread's output quad column

    const float2 d2 = *reinterpret_cast<const float2*>(dxdy + 2 * b);
    const float ndx = -d2.y, ndy = -d2.x;   // dy = d2.x, dx = d2.y
    const float kxf = floorf(ndx); const int kx = (int)kxf; const float fx = ndx - kxf;
    const float kyf = floorf(ndy); const int ky = (int)kyf; const float fy = ndy - kyf;

    const int m  = kx & 3;                  // uniform across all threads
    const int a0 = cq + kx - m;             // 4-aligned input start

    const size_t base = (size_t)b * (H * W);
    const float* __restrict__ imb = img + base;
    float* __restrict__ outp = out + base + (size_t)(yb + h0) * W + cq;

    const int ybase = yb + ky + h0;

    switch (m) {
        case 0: run_pair<0>(imb, outp, ybase, a0, fx, fy); break;
        case 1: run_pair<1>(imb, outp, ybase, a0, fx, fy); break;
        case 2: run_pair<2>(imb, outp, ybase, a0, fx, fy); break;
        default: run_pair<3>(imb, outp, ybase, a0, fx, fy); break;
    }
}

extern "C" void kernel_launch(void* const* d_in, const int* in_sizes, int n_in,
                              void* d_out, int out_size) {
    const float* images = (const float*)d_in[0];  // (256,512,512,1)
    const float* dxdy   = (const float*)d_in[1];  // (256,2)
    float* out = (float*)d_out;                   // (256,512,512)

    const int B = in_sizes[1] / 2;                // 256
    dim3 grid(H / 16, B);
    shift_bilinear_kernel<<<grid, NTHREADS>>>(images, dxdy, out);
}